// round 13
// baseline (speedup 1.0000x reference)
#include <cuda_runtime.h>
#include <cuda_fp16.h>
#include <cstdint>

#define NB 1024
#define QDIM 64
#define DDIM 512
#define EDIM 128
#define DCH 64
#define NCHUNK 8
#define NTHREADS 256
#define VMAX 100000

#define AROWB 272                 /* bytes per fp16 tile row: 256 + 16 pad */
#define MST 72                    /* Ms row stride in floats: 72%32==8 -> conflict-free */
#define MSSZ 18432                /* one Ms buffer: 64*72*4 */

// byte offsets in dynamic smem
#define AS_B   0                  /* queries fp16 tile 64x272B = 17408 */
#define B0_B   17408              /* docs tile buf0 64x272B */
#define B1_B   34816              /* docs tile buf1 */
#define MS0_B  52224              /* M tile buf0 */
#define MS1_B  70656              /* M tile buf1 */
#define QID_B  89088              /* 64 ints */
#define DID_B  89344              /* 4 x 64 ints ring = 1024 */
#define FE_B   90368              /* 24 floats */
#define HID_B  90464              /* 16 floats */
#define SMEM_BYTES 90528          /* 2 CTAs/SM */
#define LF_B   MS0_B              /* per-q feats alias Ms0 after the loop */

__device__ float g_logits[2 * NB];
__device__ __align__(16) uint2 g_embh[VMAX * 32];   // prescaled fp16 table, 256B/row

__device__ __forceinline__ float ex2f(float x) {
    float y; asm("ex2.approx.ftz.f32 %0, %1;" : "=f"(y) : "f"(x)); return y;
}
__device__ __forceinline__ uint32_t h2u(__half2 h) {
    union { __half2 h; uint32_t u; } c; c.h = h; return c.u;
}
__device__ __forceinline__ uint32_t smem_u32(const void* p) {
    uint32_t a;
    asm("{ .reg .u64 t; cvta.to.shared.u64 t, %1; cvt.u32.u64 %0, t; }" : "=r"(a) : "l"(p));
    return a;
}
__device__ __forceinline__ void ldsm_x4(uint32_t r[4], uint32_t addr) {
    asm volatile("ldmatrix.sync.aligned.m8n8.x4.shared.b16 {%0,%1,%2,%3}, [%4];"
                 : "=r"(r[0]), "=r"(r[1]), "=r"(r[2]), "=r"(r[3]) : "r"(addr));
}
__device__ __forceinline__ void mma_fp16(float c[4], const uint32_t a[4],
                                         uint32_t b0, uint32_t b1) {
    asm volatile(
        "mma.sync.aligned.m16n8k16.row.col.f32.f16.f16.f32 "
        "{%0,%1,%2,%3}, {%4,%5,%6,%7}, {%8,%9}, {%0,%1,%2,%3};"
        : "+f"(c[0]), "+f"(c[1]), "+f"(c[2]), "+f"(c[3])
        : "r"(a[0]), "r"(a[1]), "r"(a[2]), "r"(a[3]), "r"(b0), "r"(b1));
}

// Gaussian ratio-chain pooling, one element
__device__ __forceinline__ void pool1(float u, int did, int qsent,
                                      float (&acc)[20], int& mcnt) {
    float x  = u * 14.426950408889634f;
    float z  = ex2f(x);                                 // exp(10u)
    float iz = ex2f(-x);                                // exp(-10u)
    float p  = fmaf(u, -72.13475204444819f, 7.213475204444819f);
    float k0 = ex2f(fmaf(u, p, -0.18033688011112047f)); // anchor j=10
    acc[10] += k0;
    float tt = k0;
    tt *= z;  acc[11] += tt;  tt *= z;  acc[12] += tt;
    tt *= z;  acc[13] += tt;  tt *= z;  acc[14] += tt;
    tt *= z;  acc[15] += tt;  tt *= z;  acc[16] += tt;
    tt *= z;  acc[17] += tt;  tt *= z;  acc[18] += tt;
    tt *= z;  acc[19] += tt;
    tt = k0;
    tt *= iz; acc[9]  += tt;  tt *= iz; acc[8]  += tt;
    tt *= iz; acc[7]  += tt;  tt *= iz; acc[6]  += tt;
    tt *= iz; acc[5]  += tt;  tt *= iz; acc[4]  += tt;
    tt *= iz; acc[3]  += tt;  tt *= iz; acc[2]  += tt;
    tt *= iz; acc[1]  += tt;  tt *= iz; acc[0]  += tt;
    mcnt += (did == qsent);                             // exact kernel, alu pipe
}

// ---------------- preprocess: prescale vocab by inv-norm, store fp16 ----------------
__global__ void __launch_bounds__(256) knrm_prep(const float* __restrict__ emb, int V)
{
    int row0 = blockIdx.x * 16 + (threadIdx.x >> 5) * 2;
    int lane = threadIdx.x & 31;
    if (row0 >= V) return;
    const float4* emb4 = (const float4*)emb;
    float4 v0 = emb4[(size_t)row0 * 32 + lane];
    float4 v1 = (row0 + 1 < V) ? emb4[(size_t)(row0 + 1) * 32 + lane]
                               : make_float4(0.f, 0.f, 0.f, 0.f);
    float s0 = fmaf(v0.x, v0.x, fmaf(v0.y, v0.y, fmaf(v0.z, v0.z, v0.w * v0.w)));
    float s1 = fmaf(v1.x, v1.x, fmaf(v1.y, v1.y, fmaf(v1.z, v1.z, v1.w * v1.w)));
    #pragma unroll
    for (int o = 16; o; o >>= 1) {
        s0 += __shfl_xor_sync(0xffffffffu, s0, o);
        s1 += __shfl_xor_sync(0xffffffffu, s1, o);
    }
    float c0 = (s0 > 0.f) ? rsqrtf(s0) : 0.f;
    float c1 = (s1 > 0.f) ? rsqrtf(s1) : 0.f;
    g_embh[row0 * 32 + lane] = make_uint2(h2u(__floats2half2_rn(v0.x * c0, v0.y * c0)),
                                          h2u(__floats2half2_rn(v0.z * c0, v0.w * c0)));
    if (row0 + 1 < V)
        g_embh[(row0 + 1) * 32 + lane] = make_uint2(h2u(__floats2half2_rn(v1.x * c1, v1.y * c1)),
                                                    h2u(__floats2half2_rn(v1.z * c1, v1.w * c1)));
}

__global__ void __launch_bounds__(NTHREADS, 2) knrm_main(
    const int* __restrict__ q1, const int* __restrict__ d1,
    const int* __restrict__ q2, const int* __restrict__ d2,
    const float* __restrict__ W0, const float* __restrict__ b0,
    const float* __restrict__ W1, const float* __restrict__ b1,
    const float* __restrict__ W2, const float* __restrict__ b2)
{
    extern __shared__ char smc[];
    const int b  = blockIdx.x;
    const int pr = blockIdx.y;
    const int* qi = pr ? q2 : q1;
    const int* di = pr ? d2 : d1;

    const int tid  = threadIdx.x;
    const int lane = tid & 31;
    const int warp = tid >> 5;
    const int g    = lane >> 2;
    const int t    = lane & 3;

    int*   qids = (int*)(smc + QID_B);
    int*   dids = (int*)(smc + DID_B);
    float* fe   = (float*)(smc + FE_B);
    float* hid  = (float*)(smc + HID_B);
    float* lf   = (float*)(smc + LF_B);
    const uint32_t smb = smem_u32(smc);

    // ---------------- gather queries + doc chunk 0 ----------------
    #pragma unroll
    for (int r = 0; r < 8; r++) {
        int q   = warp * 8 + r;
        int idx = __ldg(&qi[b * QDIM + q]);
        uint2 pk = __ldg(&g_embh[idx * 32 + lane]);
        *(uint2*)(smc + AS_B + q * AROWB + lane * 8) = pk;
        if (lane == 0) qids[q] = idx;
    }
    #pragma unroll
    for (int i = 0; i < 8; i++) {
        int d   = warp * 8 + i;
        int idx = __ldg(&di[b * DDIM + d]);
        uint2 pk = __ldg(&g_embh[idx * 32 + lane]);
        *(uint2*)(smc + B0_B + d * AROWB + lane * 8) = pk;
        if (lane == 0) dids[d] = idx;
    }
    __syncthreads();

    // warp tiling: 2(q) x 4(d); warp tile 32q x 16d
    const int q0w = (warp >> 2) * 32;
    const int d0w = (warp & 3) * 16;
    const int pq  = tid >> 2;
    const int qid_my = qids[pq];
    const int qsent  = (qid_my == 0) ? -1 : qid_my;

    float acc[20];
    #pragma unroll
    for (int j = 0; j < 20; j++) acc[j] = 0.f;
    int mcnt = 0;

    // ldmatrix lane addresses (B0 base; add (p^1)*17408 for buffer)
    const int arow = q0w + (lane & 7) + ((lane >> 3) & 1) * 8;
    const uint32_t aaddr0 = smb + AS_B + (uint32_t)(arow * AROWB + ((lane >> 4) & 1) * 16);
    const uint32_t aaddr1 = aaddr0 + 16 * AROWB;
    const int brow = d0w + (lane & 7) + ((lane >> 4) & 1) * 8;
    const uint32_t baddr0 = smb + B0_B + (uint32_t)(brow * AROWB + ((lane >> 3) & 1) * 16);

    // ---------------- prologue: GEMM(0) -> Ms0; gather chunk1 -> B1 ----------------
    {
        float c[2][2][4];
        #pragma unroll
        for (int i = 0; i < 2; i++)
            #pragma unroll
            for (int j = 0; j < 2; j++)
                #pragma unroll
                for (int r = 0; r < 4; r++) c[i][j][r] = 0.f;
        #pragma unroll
        for (int ks = 0; ks < 8; ks++) {
            const uint32_t ko = 32u * ks;
            uint32_t a0[4], a1[4], bb[4];
            ldsm_x4(a0, aaddr0 + ko);
            ldsm_x4(a1, aaddr1 + ko);
            ldsm_x4(bb, baddr0 + ko);
            mma_fp16(c[0][0], a0, bb[0], bb[1]);
            mma_fp16(c[0][1], a0, bb[2], bb[3]);
            mma_fp16(c[1][0], a1, bb[0], bb[1]);
            mma_fp16(c[1][1], a1, bb[2], bb[3]);
        }
        float* Msw = (float*)(smc + MS0_B);
        #pragma unroll
        for (int i = 0; i < 2; i++) {
            int r0 = q0w + 16 * i + g;
            #pragma unroll
            for (int j = 0; j < 2; j++) {
                int col = d0w + 8 * j + 2 * t;
                *(float2*)&Msw[r0 * MST + col]       = make_float2(c[i][j][0], c[i][j][1]);
                *(float2*)&Msw[(r0 + 8) * MST + col] = make_float2(c[i][j][2], c[i][j][3]);
            }
        }
        int* didn = dids + DCH;
        #pragma unroll
        for (int i = 0; i < 8; i++) {
            int d   = warp * 8 + i;
            int idx = __ldg(&di[b * DDIM + DCH + d]);
            uint2 pk = __ldg(&g_embh[idx * 32 + lane]);
            *(uint2*)(smc + B1_B + d * AROWB + lane * 8) = pk;
            if (lane == 0) didn[d] = idx;
        }
    }
    __syncthreads();

    // ---------------- fused main loop: pooling(ch) interleaved with GEMM(ch+1) ----------------
    for (int ch = 0; ch < NCHUNK - 1; ch++) {
        const int p = ch & 1;
        const float* Msr = (const float*)(smc + MS0_B + p * MSSZ);
        const int*   didc = dids + (ch & 3) * DCH;
        const uint32_t bofs = (uint32_t)((p ^ 1) * (B1_B - B0_B));   // GEMM reads B[p^1]

        float c[2][2][4];
        #pragma unroll
        for (int i = 0; i < 2; i++)
            #pragma unroll
            for (int j = 0; j < 2; j++)
                #pragma unroll
                for (int r = 0; r < 4; r++) c[i][j][r] = 0.f;

        #pragma unroll
        for (int ks = 0; ks < 8; ks++) {
            const uint32_t ko = 32u * ks;
            uint32_t a0[4], a1[4], bb[4];
            ldsm_x4(a0, aaddr0 + ko);
            ldsm_x4(a1, aaddr1 + ko);
            ldsm_x4(bb, baddr0 + bofs + ko);
            mma_fp16(c[0][0], a0, bb[0], bb[1]);
            mma_fp16(c[0][1], a0, bb[2], bb[3]);
            mma_fp16(c[1][0], a1, bb[0], bb[1]);
            mma_fp16(c[1][1], a1, bb[2], bb[3]);

            // pooling iteration ks of chunk ch (fills the fma-pipe issue slots)
            float2 uu = *(const float2*)&Msr[pq * MST + 2 * t + 8 * ks];
            int2   dd = *(const int2*)&didc[2 * t + 8 * ks];
            pool1(uu.x, dd.x, qsent, acc, mcnt);
            pool1(uu.y, dd.y, qsent, acc, mcnt);
        }

        // stage chunk ch+1 -> Ms[p^1]
        float* Msw = (float*)(smc + MS0_B + (p ^ 1) * MSSZ);
        #pragma unroll
        for (int i = 0; i < 2; i++) {
            int r0 = q0w + 16 * i + g;
            #pragma unroll
            for (int j = 0; j < 2; j++) {
                int col = d0w + 8 * j + 2 * t;
                *(float2*)&Msw[r0 * MST + col]       = make_float2(c[i][j][0], c[i][j][1]);
                *(float2*)&Msw[(r0 + 8) * MST + col] = make_float2(c[i][j][2], c[i][j][3]);
            }
        }

        // gather chunk ch+2 -> B[p] (disjoint from B[p^1] just read)
        if (ch < NCHUNK - 2) {
            int* didn = dids + ((ch + 2) & 3) * DCH;
            #pragma unroll
            for (int i = 0; i < 8; i++) {
                int d   = warp * 8 + i;
                int idx = __ldg(&di[b * DDIM + (ch + 2) * DCH + d]);
                uint2 pk = __ldg(&g_embh[idx * 32 + lane]);
                *(uint2*)(smc + B0_B + p * (B1_B - B0_B) + d * AROWB + lane * 8) = pk;
                if (lane == 0) didn[d] = idx;
            }
        }
        __syncthreads();
    }

    // ---------------- epilogue: pooling of chunk 7 (Ms[1], dids ring slot 3) ----------------
    {
        const float* Msr = (const float*)(smc + MS0_B + MSSZ);
        const int*   didc = dids + 3 * DCH;
        #pragma unroll
        for (int ks = 0; ks < 8; ks++) {
            float2 uu = *(const float2*)&Msr[pq * MST + 2 * t + 8 * ks];
            int2   dd = *(const int2*)&didc[2 * t + 8 * ks];
            pool1(uu.x, dd.x, qsent, acc, mcnt);
            pool1(uu.y, dd.y, qsent, acc, mcnt);
        }
    }

    // deferred chain scaling: k_j = k0 * z^m * exp(-m(m+1)/2)
    {
        const float E1  = 0.36787944117144233f,   E3  = 0.049787068367863944f;
        const float E6  = 0.0024787521766663585f, E10 = 4.5399929762484854e-05f;
        const float E15 = 3.059023205018258e-07f, E21 = 7.582560427911907e-10f;
        const float E28 = 6.914400106940203e-13f, E36 = 2.319522830243569e-16f;
        const float E45 = 2.8625185805493937e-20f;
        acc[11] *= E1;  acc[12] *= E3;  acc[13] *= E6;  acc[14] *= E10;
        acc[15] *= E15; acc[16] *= E21; acc[17] *= E28; acc[18] *= E36; acc[19] *= E45;
        acc[8]  *= E1;  acc[7]  *= E3;  acc[6]  *= E6;  acc[5]  *= E10;
        acc[4]  *= E15; acc[3]  *= E21; acc[2]  *= E28; acc[1]  *= E36; acc[0]  *= E45;
    }
    float acc20 = (float)mcnt;

    // reduce across the 4 d-lanes, log1p per q, reduce over q
    #pragma unroll
    for (int j = 0; j < 20; j++) {
        acc[j] += __shfl_xor_sync(0xffffffffu, acc[j], 1);
        acc[j] += __shfl_xor_sync(0xffffffffu, acc[j], 2);
    }
    acc20 += __shfl_xor_sync(0xffffffffu, acc20, 1);
    acc20 += __shfl_xor_sync(0xffffffffu, acc20, 2);
    __syncthreads();           // all pooling reads done; lf aliases Ms0
    if ((tid & 3) == 0) {
        #pragma unroll
        for (int j = 0; j < 20; j++) lf[pq * 22 + j] = log1pf(acc[j]);
        lf[pq * 22 + 20] = log1pf(acc20);
    }
    __syncthreads();
    if (tid < 21) {
        float s = 0.f;
        for (int q = 0; q < QDIM; q++) s += lf[q * 22 + tid];
        fe[tid] = s;
    }
    __syncthreads();

    // tiny MLP (warp 0)
    if (warp == 0) {
        if (lane < 10) {
            float s = __ldg(&b0[lane]);
            #pragma unroll
            for (int j = 0; j < 21; j++) s = fmaf(fe[j], __ldg(&W0[lane * 21 + j]), s);
            hid[lane] = fmaxf(s, 0.f);
        }
        __syncwarp();
        if (lane < 5) {
            float s = __ldg(&b1[lane]);
            #pragma unroll
            for (int j = 0; j < 10; j++) s = fmaf(hid[j], __ldg(&W1[lane * 10 + j]), s);
            hid[10 + lane] = fmaxf(s, 0.f);
        }
        __syncwarp();
        if (lane == 0) {
            float s = __ldg(&b2[0]);
            #pragma unroll
            for (int j = 0; j < 5; j++) s = fmaf(hid[10 + j], __ldg(&W2[j]), s);
            g_logits[pr * NB + b] = s;
        }
    }
}

__global__ void knrm_final(float* __restrict__ out)
{
    int i = blockIdx.x * blockDim.x + threadIdx.x;
    if (i < NB) {
        float z = g_logits[NB + i] - g_logits[i];   // -(l1 - l2)
        out[i] = 1.0f / (1.0f + expf(z));
    }
}

extern "C" void kernel_launch(void* const* d_in, const int* in_sizes, int n_in,
                              void* d_out, int out_size)
{
    const int*   q1  = (const int*)d_in[0];
    const int*   d1  = (const int*)d_in[1];
    const int*   q2  = (const int*)d_in[2];
    const int*   d2  = (const int*)d_in[3];
    const float* emb = (const float*)d_in[4];
    const float* W0  = (const float*)d_in[5];
    const float* b0  = (const float*)d_in[6];
    const float* W1  = (const float*)d_in[7];
    const float* b1  = (const float*)d_in[8];
    const float* W2  = (const float*)d_in[9];
    const float* b2  = (const float*)d_in[10];
    const int V = in_sizes[4] / EDIM;

    cudaFuncSetAttribute(knrm_main, cudaFuncAttributeMaxDynamicSharedMemorySize, SMEM_BYTES);

    knrm_prep<<<(V + 15) / 16, 256>>>(emb, V);
    dim3 grid(NB, 2);
    knrm_main<<<grid, NTHREADS, SMEM_BYTES>>>(q1, d1, q2, d2,
                                              W0, b0, W1, b1, W2, b2);
    knrm_final<<<NB / 256, 256>>>((float*)d_out);
}

// round 14
// speedup vs baseline: 1.0791x; 1.0791x over previous
#include <cuda_runtime.h>
#include <cuda_fp16.h>
#include <cstdint>

#define NB 1024
#define QDIM 64
#define DDIM 512
#define EDIM 128
#define DCH 64
#define NCHUNK 8
#define NTHREADS 256
#define VMAX 100000

#define AROWB 272                 /* bytes per fp16 tile row: 256 + 16 pad */
#define MST 72                    /* Ms row stride in floats: 72%32==8 -> conflict-free */

// byte offsets in dynamic smem
#define AS_B   0                  /* queries fp16 tile 64x272B = 17408 */
#define BS_B   17408              /* docs tile 64x272B = 17408 */
#define MS_B   34816              /* M tile 64x72 floats = 18432 */
#define QID_B  53248              /* 64 ints */
#define DID_B  53504              /* 2 x 64 ints = 512 */
#define FE_B   54016              /* 24 floats */
#define HID_B  54112              /* 16 floats */
#define SMEM_BYTES 54176          /* 3 CTAs/SM */
#define LF_B   MS_B               /* per-q feats alias Ms after the loop */

__device__ float g_logits[2 * NB];
__device__ __align__(16) uint2 g_embh[VMAX * 32];   // prescaled fp16 table, 256B/row

__device__ __forceinline__ float ex2f(float x) {
    float y; asm("ex2.approx.ftz.f32 %0, %1;" : "=f"(y) : "f"(x)); return y;
}
__device__ __forceinline__ uint32_t h2u(__half2 h) {
    union { __half2 h; uint32_t u; } c; c.h = h; return c.u;
}
__device__ __forceinline__ uint32_t smem_u32(const void* p) {
    uint32_t a;
    asm("{ .reg .u64 t; cvta.to.shared.u64 t, %1; cvt.u32.u64 %0, t; }" : "=r"(a) : "l"(p));
    return a;
}
__device__ __forceinline__ void ldsm_x4(uint32_t r[4], uint32_t addr) {
    asm volatile("ldmatrix.sync.aligned.m8n8.x4.shared.b16 {%0,%1,%2,%3}, [%4];"
                 : "=r"(r[0]), "=r"(r[1]), "=r"(r[2]), "=r"(r[3]) : "r"(addr));
}
__device__ __forceinline__ void mma_fp16(float c[4], const uint32_t a[4],
                                         uint32_t b0, uint32_t b1) {
    asm volatile(
        "mma.sync.aligned.m16n8k16.row.col.f32.f16.f16.f32 "
        "{%0,%1,%2,%3}, {%4,%5,%6,%7}, {%8,%9}, {%0,%1,%2,%3};"
        : "+f"(c[0]), "+f"(c[1]), "+f"(c[2]), "+f"(c[3])
        : "r"(a[0]), "r"(a[1]), "r"(a[2]), "r"(a[3]), "r"(b0), "r"(b1));
}

// ---------------- preprocess: prescale vocab by inv-norm, store fp16 ----------------
__global__ void __launch_bounds__(256) knrm_prep(const float* __restrict__ emb, int V)
{
    int row0 = blockIdx.x * 16 + (threadIdx.x >> 5) * 2;
    int lane = threadIdx.x & 31;
    if (row0 >= V) return;
    const float4* emb4 = (const float4*)emb;
    float4 v0 = emb4[(size_t)row0 * 32 + lane];
    float4 v1 = (row0 + 1 < V) ? emb4[(size_t)(row0 + 1) * 32 + lane]
                               : make_float4(0.f, 0.f, 0.f, 0.f);
    float s0 = fmaf(v0.x, v0.x, fmaf(v0.y, v0.y, fmaf(v0.z, v0.z, v0.w * v0.w)));
    float s1 = fmaf(v1.x, v1.x, fmaf(v1.y, v1.y, fmaf(v1.z, v1.z, v1.w * v1.w)));
    #pragma unroll
    for (int o = 16; o; o >>= 1) {
        s0 += __shfl_xor_sync(0xffffffffu, s0, o);
        s1 += __shfl_xor_sync(0xffffffffu, s1, o);
    }
    float c0 = (s0 > 0.f) ? rsqrtf(s0) : 0.f;
    float c1 = (s1 > 0.f) ? rsqrtf(s1) : 0.f;
    g_embh[row0 * 32 + lane] = make_uint2(h2u(__floats2half2_rn(v0.x * c0, v0.y * c0)),
                                          h2u(__floats2half2_rn(v0.z * c0, v0.w * c0)));
    if (row0 + 1 < V)
        g_embh[(row0 + 1) * 32 + lane] = make_uint2(h2u(__floats2half2_rn(v1.x * c1, v1.y * c1)),
                                                    h2u(__floats2half2_rn(v1.z * c1, v1.w * c1)));
}

__global__ void __launch_bounds__(NTHREADS, 3) knrm_main(
    const int* __restrict__ q1, const int* __restrict__ d1,
    const int* __restrict__ q2, const int* __restrict__ d2,
    const float* __restrict__ W0, const float* __restrict__ b0,
    const float* __restrict__ W1, const float* __restrict__ b1,
    const float* __restrict__ W2, const float* __restrict__ b2)
{
    extern __shared__ char smc[];
    const int b  = blockIdx.x;
    const int pr = blockIdx.y;
    const int* qi = pr ? q2 : q1;
    const int* di = pr ? d2 : d1;

    const int tid  = threadIdx.x;
    const int lane = tid & 31;
    const int warp = tid >> 5;
    const int g    = lane >> 2;
    const int t    = lane & 3;

    float* Ms   = (float*)(smc + MS_B);
    int*   qids = (int*)(smc + QID_B);
    int*   dids = (int*)(smc + DID_B);
    float* fe   = (float*)(smc + FE_B);
    float* hid  = (float*)(smc + HID_B);
    float* lf   = (float*)(smc + LF_B);
    const uint32_t smb = smem_u32(smc);

    // ---------------- gather queries (prescaled fp16 rows) ----------------
    #pragma unroll
    for (int r = 0; r < 8; r++) {
        int q   = warp * 8 + r;
        int idx = __ldg(&qi[b * QDIM + q]);
        uint2 pk = __ldg(&g_embh[idx * 32 + lane]);
        *(uint2*)(smc + AS_B + q * AROWB + lane * 8) = pk;
        if (lane == 0) qids[q] = idx;
    }
    // gather doc chunk 0
    #pragma unroll
    for (int i = 0; i < 8; i++) {
        int d   = warp * 8 + i;
        int idx = __ldg(&di[b * DDIM + d]);
        uint2 pk = __ldg(&g_embh[idx * 32 + lane]);
        *(uint2*)(smc + BS_B + d * AROWB + lane * 8) = pk;
        if (lane == 0) dids[d] = idx;
    }
    __syncthreads();

    // warp tiling: 2(q) x 4(d); warp tile 32q x 16d
    const int q0w = (warp >> 2) * 32;
    const int d0w = (warp & 3) * 16;
    const int pq  = tid >> 2;                 // pooling q row
    const int qid_my = qids[pq];
    const int qsent  = (qid_my == 0) ? -1 : qid_my;

    float acc[21];
    #pragma unroll
    for (int j = 0; j < 21; j++) acc[j] = 0.f;

    // ldmatrix lane addresses
    // A x4 tiles: [q0..7|k0), (q8..15|k0), (q0..7|k16B), (q8..15|k16B)]
    const int arow = q0w + (lane & 7) + ((lane >> 3) & 1) * 8;
    const uint32_t aaddr0 = smb + AS_B + (uint32_t)(arow * AROWB + ((lane >> 4) & 1) * 16);
    const uint32_t aaddr1 = aaddr0 + 16 * AROWB;
    // B x4 tiles: [d0..7|k0), (d0..7|k16B), (d8..15|k0), (d8..15|k16B)]
    const int brow = d0w + (lane & 7) + ((lane >> 4) & 1) * 8;
    const uint32_t baddr = smb + BS_B + (uint32_t)(brow * AROWB + ((lane >> 3) & 1) * 16);

    for (int ch = 0; ch < NCHUNK; ch++) {
        // ------------- 64x64x128 fp16 m16n8k16 GEMM (warp: 32q x 16d) -------------
        float c[2][2][4];
        #pragma unroll
        for (int i = 0; i < 2; i++)
            #pragma unroll
            for (int j = 0; j < 2; j++)
                #pragma unroll
                for (int r = 0; r < 4; r++) c[i][j][r] = 0.f;

        #pragma unroll
        for (int ks = 0; ks < 8; ks++) {
            const uint32_t ko = 32u * ks;
            uint32_t a0[4], a1[4], bb[4];
            ldsm_x4(a0, aaddr0 + ko);
            ldsm_x4(a1, aaddr1 + ko);
            ldsm_x4(bb, baddr + ko);
            mma_fp16(c[0][0], a0, bb[0], bb[1]);
            mma_fp16(c[0][1], a0, bb[2], bb[3]);
            mma_fp16(c[1][0], a1, bb[0], bb[1]);
            mma_fp16(c[1][1], a1, bb[2], bb[3]);
        }

        // ------------- stage M tile -------------
        #pragma unroll
        for (int i = 0; i < 2; i++) {
            int r0 = q0w + 16 * i + g;
            #pragma unroll
            for (int j = 0; j < 2; j++) {
                int col = d0w + 8 * j + 2 * t;
                *(float2*)&Ms[r0 * MST + col]       = make_float2(c[i][j][0], c[i][j][1]);
                *(float2*)&Ms[(r0 + 8) * MST + col] = make_float2(c[i][j][2], c[i][j][3]);
            }
        }
        __syncthreads();   // Ms ready; all GEMM reads of B done

        // ------------- gather chunk ch+1 (overlaps pooling; writes B) -------------
        if (ch < NCHUNK - 1) {
            int* didn = dids + ((ch + 1) & 1) * DCH;
            #pragma unroll
            for (int i = 0; i < 8; i++) {
                int d   = warp * 8 + i;
                int idx = __ldg(&di[b * DDIM + (ch + 1) * DCH + d]);
                uint2 pk = __ldg(&g_embh[idx * 32 + lane]);
                *(uint2*)(smc + BS_B + d * AROWB + lane * 8) = pk;
                if (lane == 0) didn[d] = idx;
            }
        }

        // ------------- Gaussian pooling: ratio chain + deferred scaling -------------
        const int* didc = dids + (ch & 1) * DCH;
        #pragma unroll 2
        for (int it = 0; it < 8; it++) {
            float2 uu = *(const float2*)&Ms[pq * MST + 2 * t + 8 * it];
            int2   dd = *(const int2*)&didc[2 * t + 8 * it];
            #pragma unroll
            for (int e = 0; e < 2; e++) {
                float u   = e ? uu.y : uu.x;
                int   did = e ? dd.y : dd.x;
                float x   = u * 14.426950408889634f;
                float z   = ex2f(x);                                 // exp(10u)
                float iz  = ex2f(-x);                                // exp(-10u)
                // k0 = exp(-50(u-0.05)^2) via 2xFFMA polynomial (log2-domain)
                float p   = fmaf(u, -72.13475204444819f, 7.213475204444819f);
                float k0  = ex2f(fmaf(u, p, -0.18033688011112047f));
                acc[10] += k0;
                float tt = k0;
                tt *= z;  acc[11] += tt;  tt *= z;  acc[12] += tt;
                tt *= z;  acc[13] += tt;  tt *= z;  acc[14] += tt;
                tt *= z;  acc[15] += tt;  tt *= z;  acc[16] += tt;
                tt *= z;  acc[17] += tt;  tt *= z;  acc[18] += tt;
                tt *= z;  acc[19] += tt;
                tt = k0;
                tt *= iz; acc[9]  += tt;  tt *= iz; acc[8]  += tt;
                tt *= iz; acc[7]  += tt;  tt *= iz; acc[6]  += tt;
                tt *= iz; acc[5]  += tt;  tt *= iz; acc[4]  += tt;
                tt *= iz; acc[3]  += tt;  tt *= iz; acc[2]  += tt;
                tt *= iz; acc[1]  += tt;  tt *= iz; acc[0]  += tt;
                if (did == qsent) acc[20] += 1.0f;   // exact-match kernel (sigma=1e-3)
            }
        }
        __syncthreads();   // gather done before next GEMM; Ms reads done before next stage
    }

    // deferred chain scaling: k_j = k0 * z^m * exp(-m(m+1)/2)
    {
        const float E1  = 0.36787944117144233f,   E3  = 0.049787068367863944f;
        const float E6  = 0.0024787521766663585f, E10 = 4.5399929762484854e-05f;
        const float E15 = 3.059023205018258e-07f, E21 = 7.582560427911907e-10f;
        const float E28 = 6.914400106940203e-13f, E36 = 2.319522830243569e-16f;
        const float E45 = 2.8625185805493937e-20f;
        acc[11] *= E1;  acc[12] *= E3;  acc[13] *= E6;  acc[14] *= E10;
        acc[15] *= E15; acc[16] *= E21; acc[17] *= E28; acc[18] *= E36; acc[19] *= E45;
        acc[8]  *= E1;  acc[7]  *= E3;  acc[6]  *= E6;  acc[5]  *= E10;
        acc[4]  *= E15; acc[3]  *= E21; acc[2]  *= E28; acc[1]  *= E36; acc[0]  *= E45;
    }

    // reduce across the 4 d-lanes, log1p per q, reduce over q
    #pragma unroll
    for (int j = 0; j < 21; j++) {
        acc[j] += __shfl_xor_sync(0xffffffffu, acc[j], 1);
        acc[j] += __shfl_xor_sync(0xffffffffu, acc[j], 2);
    }
    __syncthreads();           // pooling reads of Ms done; lf aliases Ms
    if ((tid & 3) == 0) {
        #pragma unroll
        for (int j = 0; j < 21; j++) lf[pq * 22 + j] = log1pf(acc[j]);
    }
    __syncthreads();
    if (tid < 21) {
        float s = 0.f;
        for (int q = 0; q < QDIM; q++) s += lf[q * 22 + tid];
        fe[tid] = s;
    }
    __syncthreads();

    // tiny MLP (warp 0)
    if (warp == 0) {
        if (lane < 10) {
            float s = __ldg(&b0[lane]);
            #pragma unroll
            for (int j = 0; j < 21; j++) s = fmaf(fe[j], __ldg(&W0[lane * 21 + j]), s);
            hid[lane] = fmaxf(s, 0.f);
        }
        __syncwarp();
        if (lane < 5) {
            float s = __ldg(&b1[lane]);
            #pragma unroll
            for (int j = 0; j < 10; j++) s = fmaf(hid[j], __ldg(&W1[lane * 10 + j]), s);
            hid[10 + lane] = fmaxf(s, 0.f);
        }
        __syncwarp();
        if (lane == 0) {
            float s = __ldg(&b2[0]);
            #pragma unroll
            for (int j = 0; j < 5; j++) s = fmaf(hid[10 + j], __ldg(&W2[j]), s);
            g_logits[pr * NB + b] = s;
        }
    }
}

__global__ void knrm_final(float* __restrict__ out)
{
    int i = blockIdx.x * blockDim.x + threadIdx.x;
    if (i < NB) {
        float z = g_logits[NB + i] - g_logits[i];   // -(l1 - l2)
        out[i] = 1.0f / (1.0f + expf(z));
    }
}

extern "C" void kernel_launch(void* const* d_in, const int* in_sizes, int n_in,
                              void* d_out, int out_size)
{
    const int*   q1  = (const int*)d_in[0];
    const int*   d1  = (const int*)d_in[1];
    const int*   q2  = (const int*)d_in[2];
    const int*   d2  = (const int*)d_in[3];
    const float* emb = (const float*)d_in[4];
    const float* W0  = (const float*)d_in[5];
    const float* b0  = (const float*)d_in[6];
    const float* W1  = (const float*)d_in[7];
    const float* b1  = (const float*)d_in[8];
    const float* W2  = (const float*)d_in[9];
    const float* b2  = (const float*)d_in[10];
    const int V = in_sizes[4] / EDIM;

    cudaFuncSetAttribute(knrm_main, cudaFuncAttributeMaxDynamicSharedMemorySize, SMEM_BYTES);

    knrm_prep<<<(V + 15) / 16, 256>>>(emb, V);
    dim3 grid(NB, 2);
    knrm_main<<<grid, NTHREADS, SMEM_BYTES>>>(q1, d1, q2, d2,
                                              W0, b0, W1, b1, W2, b2);
    knrm_final<<<NB / 256, 256>>>((float*)d_out);
}